// round 12
// baseline (speedup 1.0000x reference)
#include <cuda_runtime.h>
#include <cuda_fp16.h>
#include <math.h>

#define NN 50000
#define EE 800000
#define INF 128
#define HH 64
#define KK 5
#define EPS 0.001f

// ---------------- scratch (static device globals; no allocations) ----------------
__device__ float  g_h[NN * HH];        // node hidden state (fp32, inter-layer)
__device__ __half g_hs16[NN * HH];     // hs = h@w_s, fp16 (gathered side)
__device__ float  g_hd[NN * HH];       // hd = h@w_d, fp32 (read once per node)
__device__ unsigned short g_q[NN * HH];  // final h, uint16, per-node scale sB
__device__ unsigned short g_qw[NN * HH]; // final h*w, biased uint16, per-node scale sA
__device__ float  g_sA[NN];            // src-side scale: rowmax|h*w| / 32767
__device__ float  g_sB[NN];            // dst-side scale: rowmax(h) / 65535
__device__ int    g_indeg[NN];
__device__ int    g_off[NN + 1];
__device__ int    g_cursor[NN];
__device__ int    g_ssrc[EE];          // src sorted by dst (CSR payload)
// packed weights, hi/lo split: half2 of (W[2kk][n], W[2kk+1][n])
__device__ unsigned g_Bemb_h[64 * 64], g_Bemb_l[64 * 64];       // K=128, n=0..63
__device__ unsigned g_Blin_h[2 * 32 * 128], g_Blin_l[2 * 32 * 128];  // K=64, j=0..127

// ---------------- helpers ----------------
__device__ __forceinline__ float sigm(float x) { return 1.0f / (1.0f + expf(-x)); }
__device__ __forceinline__ float softplus(float x) {
    return fmaxf(x, 0.0f) + log1pf(expf(-fabsf(x)));
}
#define MAGIC_C  8388608.0f   // 2^23
#define MAGIC_C2 8421376.0f   // 2^23 + 32768 (biased)

__device__ __forceinline__ float exlo(unsigned v) {
    return __uint_as_float(__byte_perm(v, 0x4B000000u, 0x7410));
}
__device__ __forceinline__ float exhi(unsigned v) {
    return __uint_as_float(__byte_perm(v, 0x4B000000u, 0x7432));
}
__device__ __forceinline__ unsigned packh2(float lo, float hi) {
    __half2 h = __floats2half2_rn(lo, hi);
    return *(unsigned*)&h;
}
// split (a,b) into hi half2 + lo(residual) half2
__device__ __forceinline__ void split2(float a, float b, unsigned& hi, unsigned& lo) {
    hi = packh2(a, b);
    float2 back = __half22float2(*(__half2*)&hi);
    lo = packh2(a - back.x, b - back.y);
}
__device__ __forceinline__ void mma16816(float& c0, float& c1, float& c2, float& c3,
                                         unsigned a0, unsigned a1, unsigned a2, unsigned a3,
                                         unsigned b0, unsigned b1) {
    asm volatile(
        "mma.sync.aligned.m16n8k16.row.col.f32.f16.f16.f32 "
        "{%0,%1,%2,%3},{%4,%5,%6,%7},{%8,%9},{%0,%1,%2,%3};"
        : "+f"(c0), "+f"(c1), "+f"(c2), "+f"(c3)
        : "r"(a0), "r"(a1), "r"(a2), "r"(a3), "r"(b0), "r"(b1));
}

// ---------------- weight prep: pack fp32 weights into hi/lo k-pair half2 ----------
__global__ void k_prep(const float* __restrict__ emb_w, const float* __restrict__ conv_w) {
    int i = blockIdx.x * blockDim.x + threadIdx.x;
    if (i < 64 * 64) {
        int kk = i >> 6, n = i & 63;
        unsigned hi, lo;
        split2(emb_w[(2 * kk) * HH + n], emb_w[(2 * kk + 1) * HH + n], hi, lo);
        g_Bemb_h[i] = hi; g_Bemb_l[i] = lo;
    } else if (i < 64 * 64 + 2 * 32 * 128) {
        int r = i - 64 * 64;
        int l = r >> 12;          // layer
        int q = r & 4095;
        int kk = q >> 7, j = q & 127;
        int k = 2 * kk;
        const float* W = conv_w + (size_t)l * 2 * HH * HH;
        float a, b;
        if (j < HH) { a = W[k * HH + j];             b = W[(k + 1) * HH + j]; }
        else        { a = W[(HH + k) * HH + j - HH]; b = W[(HH + k + 1) * HH + j - HH]; }
        unsigned hi, lo;
        split2(a, b, hi, lo);
        g_Blin_h[r] = hi; g_Blin_l[r] = lo;
    }
}

// ---------------- embed: h = node_feat @ emb_w + emb_b  (TC, split fp16) ---------
// block 256 = 8 warps; warp tile 16 rows x 64 cols; block 128 rows.
__global__ void k_embed(const float* __restrict__ x, const float* __restrict__ bias) {
    __shared__ unsigned sBh[64 * 72], sBl[64 * 72];  // [kk][n], pitch 72
    int t = threadIdx.x;
    for (int i = t; i < 64 * 64; i += 256) {
        int kk = i >> 6, n = i & 63;
        sBh[kk * 72 + n] = g_Bemb_h[i];
        sBl[kk * 72 + n] = g_Bemb_l[i];
    }
    __syncthreads();
    int w = t >> 5, lane = t & 31;
    int g = lane >> 2, tig = lane & 3;
    int r0 = blockIdx.x * 128 + w * 16 + g;
    int r1 = r0 + 8;
    float C[8][4] = {};
    #pragma unroll
    for (int kb = 0; kb < INF; kb += 16) {
        unsigned ah[4] = {0, 0, 0, 0}, al[4] = {0, 0, 0, 0};
        if (r0 < NN) {
            float2 v = *(const float2*)&x[r0 * INF + kb + 2 * tig];
            float2 u = *(const float2*)&x[r0 * INF + kb + 8 + 2 * tig];
            split2(v.x, v.y, ah[0], al[0]);
            split2(u.x, u.y, ah[2], al[2]);
        }
        if (r1 < NN) {
            float2 v = *(const float2*)&x[r1 * INF + kb + 2 * tig];
            float2 u = *(const float2*)&x[r1 * INF + kb + 8 + 2 * tig];
            split2(v.x, v.y, ah[1], al[1]);
            split2(u.x, u.y, ah[3], al[3]);
        }
        int kk = kb >> 1;
        #pragma unroll
        for (int n = 0; n < 8; n++) {
            unsigned bh0 = sBh[(kk + tig) * 72 + n * 8 + g];
            unsigned bh1 = sBh[(kk + 4 + tig) * 72 + n * 8 + g];
            unsigned bl0 = sBl[(kk + tig) * 72 + n * 8 + g];
            unsigned bl1 = sBl[(kk + 4 + tig) * 72 + n * 8 + g];
            mma16816(C[n][0], C[n][1], C[n][2], C[n][3], ah[0], ah[1], ah[2], ah[3], bh0, bh1);
            mma16816(C[n][0], C[n][1], C[n][2], C[n][3], al[0], al[1], al[2], al[3], bh0, bh1);
            mma16816(C[n][0], C[n][1], C[n][2], C[n][3], ah[0], ah[1], ah[2], ah[3], bl0, bl1);
        }
    }
    #pragma unroll
    for (int n = 0; n < 8; n++) {
        int j = n * 8 + 2 * tig;
        float bx = bias[j], by = bias[j + 1];
        if (r0 < NN) *(float2*)&g_h[r0 * HH + j] = make_float2(C[n][0] + bx, C[n][1] + by);
        if (r1 < NN) *(float2*)&g_h[r1 * HH + j] = make_float2(C[n][2] + bx, C[n][3] + by);
    }
}

// ---------------- lin: [hs16 | hd] = h @ [Ws | Wd]  (TC, split fp16) --------------
// block 256 = 8 warps; warp tile 16 rows x 128 cols; block 128 rows.
__global__ void k_lin(int layer) {
    __shared__ unsigned sBh[32 * 136], sBl[32 * 136];  // [kk][j], pitch 136
    int t = threadIdx.x;
    const unsigned* Blh = g_Blin_h + layer * 32 * 128;
    const unsigned* Bll = g_Blin_l + layer * 32 * 128;
    for (int i = t; i < 32 * 128; i += 256) {
        int kk = i >> 7, j = i & 127;
        sBh[kk * 136 + j] = Blh[i];
        sBl[kk * 136 + j] = Bll[i];
    }
    __syncthreads();
    int w = t >> 5, lane = t & 31;
    int g = lane >> 2, tig = lane & 3;
    int r0 = blockIdx.x * 128 + w * 16 + g;
    int r1 = r0 + 8;
    float C[16][4] = {};
    #pragma unroll
    for (int kb = 0; kb < HH; kb += 16) {
        unsigned ah[4] = {0, 0, 0, 0}, al[4] = {0, 0, 0, 0};
        if (r0 < NN) {
            float2 v = *(const float2*)&g_h[r0 * HH + kb + 2 * tig];
            float2 u = *(const float2*)&g_h[r0 * HH + kb + 8 + 2 * tig];
            split2(v.x, v.y, ah[0], al[0]);
            split2(u.x, u.y, ah[2], al[2]);
        }
        if (r1 < NN) {
            float2 v = *(const float2*)&g_h[r1 * HH + kb + 2 * tig];
            float2 u = *(const float2*)&g_h[r1 * HH + kb + 8 + 2 * tig];
            split2(v.x, v.y, ah[1], al[1]);
            split2(u.x, u.y, ah[3], al[3]);
        }
        int kk = kb >> 1;
        #pragma unroll
        for (int n = 0; n < 16; n++) {
            unsigned bh0 = sBh[(kk + tig) * 136 + n * 8 + g];
            unsigned bh1 = sBh[(kk + 4 + tig) * 136 + n * 8 + g];
            unsigned bl0 = sBl[(kk + tig) * 136 + n * 8 + g];
            unsigned bl1 = sBl[(kk + 4 + tig) * 136 + n * 8 + g];
            mma16816(C[n][0], C[n][1], C[n][2], C[n][3], ah[0], ah[1], ah[2], ah[3], bh0, bh1);
            mma16816(C[n][0], C[n][1], C[n][2], C[n][3], al[0], al[1], al[2], al[3], bh0, bh1);
            mma16816(C[n][0], C[n][1], C[n][2], C[n][3], ah[0], ah[1], ah[2], ah[3], bl0, bl1);
        }
    }
    #pragma unroll
    for (int n = 0; n < 16; n++) {
        int j = n * 8 + 2 * tig;
        if (j < HH) {  // hs -> fp16
            if (r0 < NN)
                *(__half2*)&g_hs16[r0 * HH + j] = __floats2half2_rn(C[n][0], C[n][1]);
            if (r1 < NN)
                *(__half2*)&g_hs16[r1 * HH + j] = __floats2half2_rn(C[n][2], C[n][3]);
        } else {       // hd -> fp32
            int jd = j - HH;
            if (r0 < NN) *(float2*)&g_hd[r0 * HH + jd] = make_float2(C[n][0], C[n][1]);
            if (r1 < NN) *(float2*)&g_hd[r1 * HH + jd] = make_float2(C[n][2], C[n][3]);
        }
    }
}

// ---------------- CSR build ----------------
__global__ void k_zero() {
    int i = blockIdx.x * blockDim.x + threadIdx.x;
    if (i < NN) { g_indeg[i] = 0; g_cursor[i] = 0; }
}
__global__ void k_count(const int* __restrict__ dst) {
    int e = blockIdx.x * blockDim.x + threadIdx.x;
    if (e < EE) atomicAdd(&g_indeg[dst[e]], 1);
}
__global__ void k_scan() {  // single block, 1024 threads
    __shared__ int ssum[1024];
    int t = threadIdx.x;
    const int CH = (NN + 1023) / 1024;
    int base = t * CH;
    int s = 0;
    for (int i = 0; i < CH; i++) {
        int idx = base + i;
        if (idx < NN) s += g_indeg[idx];
    }
    ssum[t] = s;
    __syncthreads();
    for (int off = 1; off < 1024; off <<= 1) {
        int v = (t >= off) ? ssum[t - off] : 0;
        __syncthreads();
        ssum[t] += v;
        __syncthreads();
    }
    int run = ssum[t] - s;  // exclusive prefix
    for (int i = 0; i < CH; i++) {
        int idx = base + i;
        if (idx < NN) { g_off[idx] = run; run += g_indeg[idx]; }
    }
    if (t == 1023) g_off[NN] = run;
}
__global__ void k_scatter(const int* __restrict__ src, const int* __restrict__ dst) {
    int e = blockIdx.x * blockDim.x + threadIdx.x;
    if (e < EE) {
        int d = dst[e];
        int p = atomicAdd(&g_cursor[d], 1);
        g_ssrc[g_off[d] + p] = src[e];
    }
}

// ---------------- gather + full node update (one warp per node) ----------------
// last==0: writes fp32 g_h.
// last==1: quantizes in-register (per-node scales) -> g_q, g_qw, g_sA, g_sB.
__global__ void k_gather_update(const float* __restrict__ cb,
                                const float* __restrict__ gamma,
                                const float* __restrict__ beta,
                                const float* __restrict__ mean,
                                const float* __restrict__ var,
                                const float* __restrict__ wrel,
                                int last) {
    int warp = (blockIdx.x * blockDim.x + threadIdx.x) >> 5;
    int lane = threadIdx.x & 31;
    if (warp >= NN) return;
    int n = warp;
    int s0 = g_off[n], s1 = g_off[n + 1];
    float a0 = 0.0f, a1 = 0.0f;
    int i = s0;
    for (; i + 3 < s1; i += 4) {
        int sA = g_ssrc[i], sB = g_ssrc[i + 1], sC = g_ssrc[i + 2], sD = g_ssrc[i + 3];
        float2 vA = __half22float2(*(const __half2*)&g_hs16[sA * HH + 2 * lane]);
        float2 vB = __half22float2(*(const __half2*)&g_hs16[sB * HH + 2 * lane]);
        float2 vC = __half22float2(*(const __half2*)&g_hs16[sC * HH + 2 * lane]);
        float2 vD = __half22float2(*(const __half2*)&g_hs16[sD * HH + 2 * lane]);
        a0 += (vA.x + vB.x) + (vC.x + vD.x);
        a1 += (vA.y + vB.y) + (vC.y + vD.y);
    }
    for (; i < s1; i++) {
        int s = g_ssrc[i];
        float2 v = __half22float2(*(const __half2*)&g_hs16[s * HH + 2 * lane]);
        a0 += v.x; a1 += v.y;
    }
    float deg = (float)(s1 - s0);
    float2 hd = *(const float2*)&g_hd[n * HH + 2 * lane];
    int j0 = 2 * lane, j1 = 2 * lane + 1;
    float agg0 = a0 + deg * (hd.x + cb[j0]);
    float agg1 = a1 + deg * (hd.y + cb[j1]);
    float2 hold = *(const float2*)&g_h[n * HH + 2 * lane];
    float x0 = sigm(agg0) + softplus(hold.x);
    float x1 = sigm(agg1) + softplus(hold.y);
    x0 = gamma[j0] * (x0 - mean[j0]) * rsqrtf(var[j0] + EPS) + beta[j0];
    x1 = gamma[j1] * (x1 - mean[j1]) * rsqrtf(var[j1] + EPS) + beta[j1];
    x0 = fmaxf(x0, 0.0f);
    x1 = fmaxf(x1, 0.0f);
    if (!last) {
        *(float2*)&g_h[n * HH + 2 * lane] = make_float2(x0, x1);
    } else {
        float w0 = wrel[j0], w1 = wrel[j1];
        float hw0 = x0 * w0, hw1 = x1 * w1;
        float m = fmaxf(x0, x1);
        float mw = fmaxf(fabsf(hw0), fabsf(hw1));
        #pragma unroll
        for (int o = 16; o; o >>= 1) {
            m  = fmaxf(m,  __shfl_xor_sync(0xffffffffu, m,  o));
            mw = fmaxf(mw, __shfl_xor_sync(0xffffffffu, mw, o));
        }
        m = fmaxf(m, 1e-20f);
        mw = fmaxf(mw, 1e-20f);
        float invq = 65535.0f / m;
        float invw = 32767.0f / mw;
        unsigned q0 = __float2uint_rn(x0 * invq);
        unsigned q1 = __float2uint_rn(x1 * invq);
        unsigned b0 = (unsigned)(__float2int_rn(hw0 * invw) + 32768);
        unsigned b1 = (unsigned)(__float2int_rn(hw1 * invw) + 32768);
        *(unsigned*)&g_q[n * HH + 2 * lane]  = q0 | (q1 << 16);
        *(unsigned*)&g_qw[n * HH + 2 * lane] = b0 | (b1 << 16);
        if (lane == 0) {
            g_sB[n] = m * (1.0f / 65535.0f);
            g_sA[n] = mw * (1.0f / 32767.0f);
        }
    }
}

// ---------------- fused scoring: pos + K negs per edge, 8 threads/edge ----------
__global__ void k_score(const int* __restrict__ src, const int* __restrict__ dst,
                        const int* __restrict__ neg_dst, float* __restrict__ out) {
    int gid = blockIdx.x * blockDim.x + threadIdx.x;
    int e = gid >> 3;
    int c = gid & 7;
    if (e >= EE) return;

    int s = src[e];
    int d = dst[e];
    int nd[KK];
    #pragma unroll
    for (int k = 0; k < KK; k++) nd[k] = neg_dst[e * KK + k];

    uint4 qs = *(const uint4*)&g_qw[s * HH + 8 * c];
    uint4 qp = *(const uint4*)&g_q[d * HH + 8 * c];
    uint4 qn[KK];
    #pragma unroll
    for (int k = 0; k < KK; k++)
        qn[k] = *(const uint4*)&g_q[nd[k] * HH + 8 * c];
    float sA = g_sA[s];
    float sBp = g_sB[d];
    float sBn[KK];
    #pragma unroll
    for (int k = 0; k < KK; k++) sBn[k] = g_sB[nd[k]];

    float aw[8];
    const unsigned* vs = (const unsigned*)&qs;
    #pragma unroll
    for (int i = 0; i < 4; i++) {
        aw[2 * i]     = exlo(vs[i]) - MAGIC_C2;
        aw[2 * i + 1] = exhi(vs[i]) - MAGIC_C2;
    }
    float awsum = ((aw[0] + aw[1]) + (aw[2] + aw[3])) +
                  ((aw[4] + aw[5]) + (aw[6] + aw[7]));
    float base = -MAGIC_C * awsum;

    {
        const unsigned* vd = (const unsigned*)&qp;
        float p = base;
        #pragma unroll
        for (int i = 0; i < 4; i++) {
            p = fmaf(aw[2 * i],     exlo(vd[i]), p);
            p = fmaf(aw[2 * i + 1], exhi(vd[i]), p);
        }
        p += __shfl_xor_sync(0xffffffffu, p, 4);
        p += __shfl_xor_sync(0xffffffffu, p, 2);
        p += __shfl_xor_sync(0xffffffffu, p, 1);
        if (c == 0) out[e] = p * (sA * sBp);
    }
    #pragma unroll
    for (int k = 0; k < KK; k++) {
        const unsigned* vd = (const unsigned*)&qn[k];
        float p = base;
        #pragma unroll
        for (int i = 0; i < 4; i++) {
            p = fmaf(aw[2 * i],     exlo(vd[i]), p);
            p = fmaf(aw[2 * i + 1], exhi(vd[i]), p);
        }
        p += __shfl_xor_sync(0xffffffffu, p, 4);
        p += __shfl_xor_sync(0xffffffffu, p, 2);
        p += __shfl_xor_sync(0xffffffffu, p, 1);
        if (c == 0) out[EE + e * KK + k] = p * (sA * sBn[k]);
    }
}

// ---------------- launch ----------------
extern "C" void kernel_launch(void* const* d_in, const int* in_sizes, int n_in,
                              void* d_out, int out_size) {
    const float* node_feat = (const float*)d_in[0];
    const float* emb_w     = (const float*)d_in[1];
    const float* emb_b     = (const float*)d_in[2];
    const float* conv_w    = (const float*)d_in[3];
    const float* conv_b    = (const float*)d_in[4];
    const float* bn_gamma  = (const float*)d_in[5];
    const float* bn_beta   = (const float*)d_in[6];
    const float* bn_mean   = (const float*)d_in[7];
    const float* bn_var    = (const float*)d_in[8];
    const float* w_rel     = (const float*)d_in[9];
    const int*   src       = (const int*)d_in[10];
    const int*   dst       = (const int*)d_in[11];
    const int*   neg_dst   = (const int*)d_in[12];
    float* out = (float*)d_out;

    // side stream + fork/join events, created once (before any capture)
    static cudaStream_t s1 = nullptr;
    static cudaEvent_t eF = nullptr, eJ = nullptr;
    if (!s1) {
        cudaStreamCreateWithFlags(&s1, cudaStreamNonBlocking);
        cudaEventCreateWithFlags(&eF, cudaEventDisableTiming);
        cudaEventCreateWithFlags(&eJ, cudaEventDisableTiming);
    }

    // fork: CSR build on s1, concurrent with prep+embed+lin0 on default stream
    cudaEventRecord(eF, 0);
    cudaStreamWaitEvent(s1, eF, 0);
    k_zero<<<(NN + 255) / 256, 256, 0, s1>>>();
    k_count<<<(EE + 255) / 256, 256, 0, s1>>>(dst);
    k_scan<<<1, 1024, 0, s1>>>();
    k_scatter<<<(EE + 255) / 256, 256, 0, s1>>>(src, dst);
    cudaEventRecord(eJ, s1);

    // weight prep + embedding + first linear (tensor cores, split-fp16)
    k_prep<<<48, 256>>>(emb_w, conv_w);
    k_embed<<<(NN + 127) / 128, 256>>>(node_feat, emb_b);
    k_lin<<<(NN + 127) / 128, 256>>>(0);

    // join: gather needs CSR
    cudaStreamWaitEvent(0, eJ, 0);

    k_gather_update<<<(NN * 32 + 255) / 256, 256>>>(
        conv_b, bn_gamma, bn_beta, bn_mean, bn_var, w_rel, 0);

    k_lin<<<(NN + 127) / 128, 256>>>(1);
    k_gather_update<<<(NN * 32 + 255) / 256, 256>>>(
        conv_b + HH, bn_gamma + HH, bn_beta + HH, bn_mean + HH, bn_var + HH,
        w_rel, 1);

    // fused scoring (uint16 dequant, per-node scales)
    k_score<<<(EE * 8 + 255) / 256, 256>>>(src, dst, neg_dst, out);
}

// round 13
// speedup vs baseline: 1.1339x; 1.1339x over previous
#include <cuda_runtime.h>
#include <cuda_fp16.h>
#include <math.h>

#define NN 50000
#define EE 800000
#define INF 128
#define HH 64
#define KK 5
#define EPS 0.001f

// ---------------- scratch (static device globals; no allocations) ----------------
__device__ float  g_h[NN * HH];        // node hidden state (fp32, inter-layer)
__device__ __half g_hs16[NN * HH];     // hs = h@w_s, fp16 (gathered side)
__device__ float  g_hd[NN * HH];       // hd = h@w_d, fp32 (read once per node)
__device__ unsigned short g_q[NN * HH];  // final h, uint16, per-node scale sB
__device__ unsigned short g_qw[NN * HH]; // final h*w, biased uint16, per-node scale sA
__device__ float  g_sA[NN];            // src-side scale: rowmax|h*w| / 32767
__device__ float  g_sB[NN];            // dst-side scale: rowmax(h) / 65535
__device__ int    g_indeg[NN];
__device__ int    g_off[NN + 1];
__device__ int    g_cursor[NN];
__device__ int    g_ssrc[EE];          // src sorted by dst (CSR payload)

// ---------------- helpers ----------------
__device__ __forceinline__ float sigm(float x) { return 1.0f / (1.0f + expf(-x)); }
__device__ __forceinline__ float softplus(float x) {
    return fmaxf(x, 0.0f) + log1pf(expf(-fabsf(x)));
}
#define MAGIC_C  8388608.0f   // 2^23
#define MAGIC_C2 8421376.0f   // 2^23 + 32768 (biased)

__device__ __forceinline__ float exlo(unsigned v) {
    return __uint_as_float(__byte_perm(v, 0x4B000000u, 0x7410));
}
__device__ __forceinline__ float exhi(unsigned v) {
    return __uint_as_float(__byte_perm(v, 0x4B000000u, 0x7432));
}
__device__ __forceinline__ unsigned packh2(float lo, float hi) {
    __half2 h = __floats2half2_rn(lo, hi);
    return *(unsigned*)&h;
}
// split (a,b) into hi half2 + lo(residual) half2
__device__ __forceinline__ void split2(float a, float b, unsigned& hi, unsigned& lo) {
    hi = packh2(a, b);
    float2 back = __half22float2(*(__half2*)&hi);
    lo = packh2(a - back.x, b - back.y);
}
__device__ __forceinline__ void mma16816(float& c0, float& c1, float& c2, float& c3,
                                         unsigned a0, unsigned a1, unsigned a2, unsigned a3,
                                         unsigned b0, unsigned b1) {
    asm volatile(
        "mma.sync.aligned.m16n8k16.row.col.f32.f16.f16.f32 "
        "{%0,%1,%2,%3},{%4,%5,%6,%7},{%8,%9},{%0,%1,%2,%3};"
        : "+f"(c0), "+f"(c1), "+f"(c2), "+f"(c3)
        : "r"(a0), "r"(a1), "r"(a2), "r"(a3), "r"(b0), "r"(b1));
}

// ---------------- embed: h = node_feat @ emb_w + emb_b  (TC, 3-term split) -------
// Undamped error path (softplus) -> keep fp32-quality via Markidis split.
// block 256 = 8 warps; warp tile 16 rows x 64 cols; block 128 rows.
__global__ void k_embed(const float* __restrict__ x, const float* __restrict__ emb_w,
                        const float* __restrict__ bias) {
    __shared__ unsigned sBh[64 * 72], sBl[64 * 72];  // [kk][n], pitch 72
    int t = threadIdx.x;
    for (int i = t; i < 64 * 64; i += 256) {
        int kk = i >> 6, n = i & 63;
        unsigned hi, lo;
        split2(emb_w[(2 * kk) * HH + n], emb_w[(2 * kk + 1) * HH + n], hi, lo);
        sBh[kk * 72 + n] = hi;
        sBl[kk * 72 + n] = lo;
    }
    __syncthreads();
    int w = t >> 5, lane = t & 31;
    int g = lane >> 2, tig = lane & 3;
    int r0 = blockIdx.x * 128 + w * 16 + g;
    int r1 = r0 + 8;
    float C[8][4] = {};
    #pragma unroll
    for (int kb = 0; kb < INF; kb += 16) {
        unsigned ah[4] = {0, 0, 0, 0}, al[4] = {0, 0, 0, 0};
        if (r0 < NN) {
            float2 v = *(const float2*)&x[r0 * INF + kb + 2 * tig];
            float2 u = *(const float2*)&x[r0 * INF + kb + 8 + 2 * tig];
            split2(v.x, v.y, ah[0], al[0]);
            split2(u.x, u.y, ah[2], al[2]);
        }
        if (r1 < NN) {
            float2 v = *(const float2*)&x[r1 * INF + kb + 2 * tig];
            float2 u = *(const float2*)&x[r1 * INF + kb + 8 + 2 * tig];
            split2(v.x, v.y, ah[1], al[1]);
            split2(u.x, u.y, ah[3], al[3]);
        }
        int kk = kb >> 1;
        #pragma unroll
        for (int n = 0; n < 8; n++) {
            unsigned bh0 = sBh[(kk + tig) * 72 + n * 8 + g];
            unsigned bh1 = sBh[(kk + 4 + tig) * 72 + n * 8 + g];
            unsigned bl0 = sBl[(kk + tig) * 72 + n * 8 + g];
            unsigned bl1 = sBl[(kk + 4 + tig) * 72 + n * 8 + g];
            mma16816(C[n][0], C[n][1], C[n][2], C[n][3], ah[0], ah[1], ah[2], ah[3], bh0, bh1);
            mma16816(C[n][0], C[n][1], C[n][2], C[n][3], al[0], al[1], al[2], al[3], bh0, bh1);
            mma16816(C[n][0], C[n][1], C[n][2], C[n][3], ah[0], ah[1], ah[2], ah[3], bl0, bl1);
        }
    }
    #pragma unroll
    for (int n = 0; n < 8; n++) {
        int j = n * 8 + 2 * tig;
        float bx = bias[j], by = bias[j + 1];
        if (r0 < NN) *(float2*)&g_h[r0 * HH + j] = make_float2(C[n][0] + bx, C[n][1] + by);
        if (r1 < NN) *(float2*)&g_h[r1 * HH + j] = make_float2(C[n][2] + bx, C[n][3] + by);
    }
}

// ---------------- lin: [hs16 | hd] = h @ [Ws | Wd]  (TC, single fp16) -------------
// Damped error path (sigmoid(agg)) -> plain fp16 MMA is enough.
// block 256 = 8 warps; warp tile 16 rows x 128 cols; block 128 rows.
__global__ void k_lin(const float* __restrict__ W /* layer slice [128][64] */) {
    __shared__ unsigned sB[32 * 136];  // [kk][j], pitch 136
    int t = threadIdx.x;
    for (int i = t; i < 32 * 128; i += 256) {
        int kk = i >> 7, j = i & 127;
        int k = 2 * kk;
        float a, b;
        if (j < HH) { a = W[k * HH + j];             b = W[(k + 1) * HH + j]; }
        else        { a = W[(HH + k) * HH + j - HH]; b = W[(HH + k + 1) * HH + j - HH]; }
        sB[kk * 136 + j] = packh2(a, b);
    }
    __syncthreads();
    int w = t >> 5, lane = t & 31;
    int g = lane >> 2, tig = lane & 3;
    int r0 = blockIdx.x * 128 + w * 16 + g;
    int r1 = r0 + 8;
    float C[16][4] = {};
    #pragma unroll
    for (int kb = 0; kb < HH; kb += 16) {
        unsigned a0 = 0, a1 = 0, a2 = 0, a3 = 0;
        if (r0 < NN) {
            float2 v = *(const float2*)&g_h[r0 * HH + kb + 2 * tig];
            float2 u = *(const float2*)&g_h[r0 * HH + kb + 8 + 2 * tig];
            a0 = packh2(v.x, v.y);
            a2 = packh2(u.x, u.y);
        }
        if (r1 < NN) {
            float2 v = *(const float2*)&g_h[r1 * HH + kb + 2 * tig];
            float2 u = *(const float2*)&g_h[r1 * HH + kb + 8 + 2 * tig];
            a1 = packh2(v.x, v.y);
            a3 = packh2(u.x, u.y);
        }
        int kk = kb >> 1;
        #pragma unroll
        for (int n = 0; n < 16; n++) {
            unsigned b0 = sB[(kk + tig) * 136 + n * 8 + g];
            unsigned b1 = sB[(kk + 4 + tig) * 136 + n * 8 + g];
            mma16816(C[n][0], C[n][1], C[n][2], C[n][3], a0, a1, a2, a3, b0, b1);
        }
    }
    #pragma unroll
    for (int n = 0; n < 16; n++) {
        int j = n * 8 + 2 * tig;
        if (j < HH) {  // hs -> fp16
            if (r0 < NN)
                *(__half2*)&g_hs16[r0 * HH + j] = __floats2half2_rn(C[n][0], C[n][1]);
            if (r1 < NN)
                *(__half2*)&g_hs16[r1 * HH + j] = __floats2half2_rn(C[n][2], C[n][3]);
        } else {       // hd -> fp32
            int jd = j - HH;
            if (r0 < NN) *(float2*)&g_hd[r0 * HH + jd] = make_float2(C[n][0], C[n][1]);
            if (r1 < NN) *(float2*)&g_hd[r1 * HH + jd] = make_float2(C[n][2], C[n][3]);
        }
    }
}

// ---------------- CSR build ----------------
__global__ void k_zero() {
    int i = blockIdx.x * blockDim.x + threadIdx.x;
    if (i < NN) { g_indeg[i] = 0; g_cursor[i] = 0; }
}
__global__ void k_count(const int* __restrict__ dst) {
    int e = blockIdx.x * blockDim.x + threadIdx.x;
    if (e < EE) atomicAdd(&g_indeg[dst[e]], 1);
}
__global__ void k_scan() {  // single block, 1024 threads
    __shared__ int ssum[1024];
    int t = threadIdx.x;
    const int CH = (NN + 1023) / 1024;
    int base = t * CH;
    int s = 0;
    for (int i = 0; i < CH; i++) {
        int idx = base + i;
        if (idx < NN) s += g_indeg[idx];
    }
    ssum[t] = s;
    __syncthreads();
    for (int off = 1; off < 1024; off <<= 1) {
        int v = (t >= off) ? ssum[t - off] : 0;
        __syncthreads();
        ssum[t] += v;
        __syncthreads();
    }
    int run = ssum[t] - s;  // exclusive prefix
    for (int i = 0; i < CH; i++) {
        int idx = base + i;
        if (idx < NN) { g_off[idx] = run; run += g_indeg[idx]; }
    }
    if (t == 1023) g_off[NN] = run;
}
__global__ void k_scatter(const int* __restrict__ src, const int* __restrict__ dst) {
    int e = blockIdx.x * blockDim.x + threadIdx.x;
    if (e < EE) {
        int d = dst[e];
        int p = atomicAdd(&g_cursor[d], 1);
        g_ssrc[g_off[d] + p] = src[e];
    }
}

// ---------------- gather + full node update (one warp per node) ----------------
// last==0: writes fp32 g_h.
// last==1: quantizes in-register (per-node scales) -> g_q, g_qw, g_sA, g_sB.
__global__ void k_gather_update(const float* __restrict__ cb,
                                const float* __restrict__ gamma,
                                const float* __restrict__ beta,
                                const float* __restrict__ mean,
                                const float* __restrict__ var,
                                const float* __restrict__ wrel,
                                int last) {
    int warp = (blockIdx.x * blockDim.x + threadIdx.x) >> 5;
    int lane = threadIdx.x & 31;
    if (warp >= NN) return;
    int n = warp;
    int s0 = g_off[n], s1 = g_off[n + 1];
    float a0 = 0.0f, a1 = 0.0f;
    int i = s0;
    for (; i + 3 < s1; i += 4) {
        int sA = g_ssrc[i], sB = g_ssrc[i + 1], sC = g_ssrc[i + 2], sD = g_ssrc[i + 3];
        float2 vA = __half22float2(*(const __half2*)&g_hs16[sA * HH + 2 * lane]);
        float2 vB = __half22float2(*(const __half2*)&g_hs16[sB * HH + 2 * lane]);
        float2 vC = __half22float2(*(const __half2*)&g_hs16[sC * HH + 2 * lane]);
        float2 vD = __half22float2(*(const __half2*)&g_hs16[sD * HH + 2 * lane]);
        a0 += (vA.x + vB.x) + (vC.x + vD.x);
        a1 += (vA.y + vB.y) + (vC.y + vD.y);
    }
    for (; i < s1; i++) {
        int s = g_ssrc[i];
        float2 v = __half22float2(*(const __half2*)&g_hs16[s * HH + 2 * lane]);
        a0 += v.x; a1 += v.y;
    }
    float deg = (float)(s1 - s0);
    float2 hd = *(const float2*)&g_hd[n * HH + 2 * lane];
    int j0 = 2 * lane, j1 = 2 * lane + 1;
    float agg0 = a0 + deg * (hd.x + cb[j0]);
    float agg1 = a1 + deg * (hd.y + cb[j1]);
    float2 hold = *(const float2*)&g_h[n * HH + 2 * lane];
    float x0 = sigm(agg0) + softplus(hold.x);
    float x1 = sigm(agg1) + softplus(hold.y);
    x0 = gamma[j0] * (x0 - mean[j0]) * rsqrtf(var[j0] + EPS) + beta[j0];
    x1 = gamma[j1] * (x1 - mean[j1]) * rsqrtf(var[j1] + EPS) + beta[j1];
    x0 = fmaxf(x0, 0.0f);
    x1 = fmaxf(x1, 0.0f);
    if (!last) {
        *(float2*)&g_h[n * HH + 2 * lane] = make_float2(x0, x1);
    } else {
        float w0 = wrel[j0], w1 = wrel[j1];
        float hw0 = x0 * w0, hw1 = x1 * w1;
        float m = fmaxf(x0, x1);
        float mw = fmaxf(fabsf(hw0), fabsf(hw1));
        #pragma unroll
        for (int o = 16; o; o >>= 1) {
            m  = fmaxf(m,  __shfl_xor_sync(0xffffffffu, m,  o));
            mw = fmaxf(mw, __shfl_xor_sync(0xffffffffu, mw, o));
        }
        m = fmaxf(m, 1e-20f);
        mw = fmaxf(mw, 1e-20f);
        float invq = 65535.0f / m;
        float invw = 32767.0f / mw;
        unsigned q0 = __float2uint_rn(x0 * invq);
        unsigned q1 = __float2uint_rn(x1 * invq);
        unsigned b0 = (unsigned)(__float2int_rn(hw0 * invw) + 32768);
        unsigned b1 = (unsigned)(__float2int_rn(hw1 * invw) + 32768);
        *(unsigned*)&g_q[n * HH + 2 * lane]  = q0 | (q1 << 16);
        *(unsigned*)&g_qw[n * HH + 2 * lane] = b0 | (b1 << 16);
        if (lane == 0) {
            g_sB[n] = m * (1.0f / 65535.0f);
            g_sA[n] = mw * (1.0f / 32767.0f);
        }
    }
}

// ---------------- fused scoring: pos + K negs per edge, 8 threads/edge ----------
__global__ void k_score(const int* __restrict__ src, const int* __restrict__ dst,
                        const int* __restrict__ neg_dst, float* __restrict__ out) {
    int gid = blockIdx.x * blockDim.x + threadIdx.x;
    int e = gid >> 3;
    int c = gid & 7;
    if (e >= EE) return;

    int s = src[e];
    int d = dst[e];
    int nd[KK];
    #pragma unroll
    for (int k = 0; k < KK; k++) nd[k] = neg_dst[e * KK + k];

    uint4 qs = *(const uint4*)&g_qw[s * HH + 8 * c];
    uint4 qp = *(const uint4*)&g_q[d * HH + 8 * c];
    uint4 qn[KK];
    #pragma unroll
    for (int k = 0; k < KK; k++)
        qn[k] = *(const uint4*)&g_q[nd[k] * HH + 8 * c];
    float sA = g_sA[s];
    float sBp = g_sB[d];
    float sBn[KK];
    #pragma unroll
    for (int k = 0; k < KK; k++) sBn[k] = g_sB[nd[k]];

    float aw[8];
    const unsigned* vs = (const unsigned*)&qs;
    #pragma unroll
    for (int i = 0; i < 4; i++) {
        aw[2 * i]     = exlo(vs[i]) - MAGIC_C2;
        aw[2 * i + 1] = exhi(vs[i]) - MAGIC_C2;
    }
    float awsum = ((aw[0] + aw[1]) + (aw[2] + aw[3])) +
                  ((aw[4] + aw[5]) + (aw[6] + aw[7]));
    float base = -MAGIC_C * awsum;

    {
        const unsigned* vd = (const unsigned*)&qp;
        float p = base;
        #pragma unroll
        for (int i = 0; i < 4; i++) {
            p = fmaf(aw[2 * i],     exlo(vd[i]), p);
            p = fmaf(aw[2 * i + 1], exhi(vd[i]), p);
        }
        p += __shfl_xor_sync(0xffffffffu, p, 4);
        p += __shfl_xor_sync(0xffffffffu, p, 2);
        p += __shfl_xor_sync(0xffffffffu, p, 1);
        if (c == 0) out[e] = p * (sA * sBp);
    }
    #pragma unroll
    for (int k = 0; k < KK; k++) {
        const unsigned* vd = (const unsigned*)&qn[k];
        float p = base;
        #pragma unroll
        for (int i = 0; i < 4; i++) {
            p = fmaf(aw[2 * i],     exlo(vd[i]), p);
            p = fmaf(aw[2 * i + 1], exhi(vd[i]), p);
        }
        p += __shfl_xor_sync(0xffffffffu, p, 4);
        p += __shfl_xor_sync(0xffffffffu, p, 2);
        p += __shfl_xor_sync(0xffffffffu, p, 1);
        if (c == 0) out[EE + e * KK + k] = p * (sA * sBn[k]);
    }
}

// ---------------- launch ----------------
extern "C" void kernel_launch(void* const* d_in, const int* in_sizes, int n_in,
                              void* d_out, int out_size) {
    const float* node_feat = (const float*)d_in[0];
    const float* emb_w     = (const float*)d_in[1];
    const float* emb_b     = (const float*)d_in[2];
    const float* conv_w    = (const float*)d_in[3];
    const float* conv_b    = (const float*)d_in[4];
    const float* bn_gamma  = (const float*)d_in[5];
    const float* bn_beta   = (const float*)d_in[6];
    const float* bn_mean   = (const float*)d_in[7];
    const float* bn_var    = (const float*)d_in[8];
    const float* w_rel     = (const float*)d_in[9];
    const int*   src       = (const int*)d_in[10];
    const int*   dst       = (const int*)d_in[11];
    const int*   neg_dst   = (const int*)d_in[12];
    float* out = (float*)d_out;

    // side stream + fork/join events, created once (before any capture)
    static cudaStream_t s1 = nullptr;
    static cudaEvent_t eF = nullptr, eJ = nullptr;
    if (!s1) {
        cudaStreamCreateWithFlags(&s1, cudaStreamNonBlocking);
        cudaEventCreateWithFlags(&eF, cudaEventDisableTiming);
        cudaEventCreateWithFlags(&eJ, cudaEventDisableTiming);
    }

    // fork: CSR build on s1, concurrent with embed+lin0 on default stream
    cudaEventRecord(eF, 0);
    cudaStreamWaitEvent(s1, eF, 0);
    k_zero<<<(NN + 255) / 256, 256, 0, s1>>>();
    k_count<<<(EE + 255) / 256, 256, 0, s1>>>(dst);
    k_scan<<<1, 1024, 0, s1>>>();
    k_scatter<<<(EE + 255) / 256, 256, 0, s1>>>(src, dst);
    cudaEventRecord(eJ, s1);

    // embedding (split fp16, fp32 quality) + first linear (single fp16, damped path)
    k_embed<<<(NN + 127) / 128, 256>>>(node_feat, emb_w, emb_b);
    k_lin<<<(NN + 127) / 128, 256>>>(conv_w);

    // join: gather needs CSR
    cudaStreamWaitEvent(0, eJ, 0);

    k_gather_update<<<(NN * 32 + 255) / 256, 256>>>(
        conv_b, bn_gamma, bn_beta, bn_mean, bn_var, w_rel, 0);

    k_lin<<<(NN + 127) / 128, 256>>>(conv_w + (size_t)2 * HH * HH);
    k_gather_update<<<(NN * 32 + 255) / 256, 256>>>(
        conv_b + HH, bn_gamma + HH, bn_beta + HH, bn_mean + HH, bn_var + HH,
        w_rel, 1);

    // fused scoring (uint16 dequant, per-node scales)
    k_score<<<(EE * 8 + 255) / 256, 256>>>(src, dst, neg_dst, out);
}